// round 1
// baseline (speedup 1.0000x reference)
#include <cuda_runtime.h>
#include <math.h>
#include <stddef.h>

#define BATCH 8
#define NT 1024
#define TD 128
#define HID 512
#define NH 8
#define HD 64

// ---------------- device scratch (static; no allocation) ----------------
__device__ unsigned g_tmax_u;
__device__ float g_twm[BATCH * NT * NT];     // adj ? exp(-0.1*(tmax-t)) : -1
__device__ float g_struct[NT * HID];
__device__ float g_bt[HID * HID];            // transposed weight staging
__device__ float g_h[BATCH * NT * HID];      // h per (b,n,[h*64+d])
__device__ float g_node[BATCH * NT * HID];   // GAT layer output
__device__ float g_esrc[BATCH * NH * NT];
__device__ float g_edst[BATCH * NH * NT];

// ---------------- small kernels ----------------
__global__ void k_init() { g_tmax_u = 0u; }

__global__ void k_tmax(const float4* __restrict__ t, int n4) {
    float m = 0.f;
    for (int i = blockIdx.x * blockDim.x + threadIdx.x; i < n4; i += gridDim.x * blockDim.x) {
        float4 v = t[i];
        m = fmaxf(m, fmaxf(fmaxf(v.x, v.y), fmaxf(v.z, v.w)));
    }
#pragma unroll
    for (int s = 16; s; s >>= 1) m = fmaxf(m, __shfl_xor_sync(0xffffffffu, m, s));
    __shared__ float sm[8];
    if ((threadIdx.x & 31) == 0) sm[threadIdx.x >> 5] = m;
    __syncthreads();
    if (threadIdx.x == 0) {
        for (int w = 1; w < 8; w++) m = fmaxf(m, sm[w]);
        atomicMax(&g_tmax_u, __float_as_uint(m));  // values >= 0 -> uint order == float order
    }
}

__global__ void k_twm(const float4* __restrict__ tm, const int4* __restrict__ adj, int n4) {
    float tmax = __uint_as_float(g_tmax_u);
    int stride = gridDim.x * blockDim.x;
    for (int i = blockIdx.x * blockDim.x + threadIdx.x; i < n4; i += stride) {
        float4 t = tm[i];
        int4 a = adj[i];
        float4 o;
        o.x = a.x ? expf(-0.1f * (tmax - t.x)) : -1.f;
        o.y = a.y ? expf(-0.1f * (tmax - t.y)) : -1.f;
        o.z = a.z ? expf(-0.1f * (tmax - t.z)) : -1.f;
        o.w = a.w ? expf(-0.1f * (tmax - t.w)) : -1.f;
        reinterpret_cast<float4*>(g_twm)[i] = o;
    }
}

// struct_W [512,128] -> Bt [128,512]
__global__ void k_transB(const float* __restrict__ sW, float* __restrict__ out) {
    int idx = blockIdx.x * 256 + threadIdx.x;  // < 128*512
    int k = idx >> 9, n = idx & 511;
    out[idx] = sW[n * TD + k];
}

// gat_W[l] [8,512,64] -> Wcat [512,512] with Wcat[k][h*64+d]
__global__ void k_transW(const float* __restrict__ gWl, float* __restrict__ out) {
    int idx = blockIdx.x * 256 + threadIdx.x;  // < 512*512
    int k = idx >> 9, c = idx & 511;
    int hh = c >> 6, d = c & 63;
    out[idx] = gWl[hh * (HID * HD) + k * HD + d];
}

// ---------------- generic 64x64 tiled fp32 GEMM: C[M,N] = A[M,K]*B[K,N] (+bias) ----------------
__global__ void k_gemm(const float* __restrict__ A, const float* __restrict__ B,
                       float* __restrict__ C, const float* __restrict__ bias,
                       int K, int N) {
    __shared__ float As[32][68];
    __shared__ float Bs[32][68];
    int t = threadIdx.x;
    int tx = t & 15, ty = t >> 4;
    int m0 = blockIdx.x * 64, n0 = blockIdx.y * 64;
    float acc[4][4] = {};
    int ar = t >> 3, akc = (t & 7) * 4;
    int bk = t >> 3, bnc = (t & 7) * 8;

    for (int kt = 0; kt < K; kt += 32) {
#pragma unroll
        for (int rr = 0; rr < 64; rr += 32) {
            float4 v = *reinterpret_cast<const float4*>(A + (size_t)(m0 + ar + rr) * K + kt + akc);
            As[akc + 0][ar + rr] = v.x;
            As[akc + 1][ar + rr] = v.y;
            As[akc + 2][ar + rr] = v.z;
            As[akc + 3][ar + rr] = v.w;
        }
        {
            const float* bp = B + (size_t)(kt + bk) * N + n0 + bnc;
            float4 v0 = *reinterpret_cast<const float4*>(bp);
            float4 v1 = *reinterpret_cast<const float4*>(bp + 4);
            *reinterpret_cast<float4*>(&Bs[bk][bnc]) = v0;
            *reinterpret_cast<float4*>(&Bs[bk][bnc + 4]) = v1;
        }
        __syncthreads();
#pragma unroll
        for (int k = 0; k < 32; k++) {
            float4 a4 = *reinterpret_cast<const float4*>(&As[k][ty * 4]);
            float4 b4 = *reinterpret_cast<const float4*>(&Bs[k][tx * 4]);
            acc[0][0] += a4.x * b4.x; acc[0][1] += a4.x * b4.y; acc[0][2] += a4.x * b4.z; acc[0][3] += a4.x * b4.w;
            acc[1][0] += a4.y * b4.x; acc[1][1] += a4.y * b4.y; acc[1][2] += a4.y * b4.z; acc[1][3] += a4.y * b4.w;
            acc[2][0] += a4.z * b4.x; acc[2][1] += a4.z * b4.y; acc[2][2] += a4.z * b4.z; acc[2][3] += a4.z * b4.w;
            acc[3][0] += a4.w * b4.x; acc[3][1] += a4.w * b4.y; acc[3][2] += a4.w * b4.z; acc[3][3] += a4.w * b4.w;
        }
        __syncthreads();
    }
    float bx = 0.f, by = 0.f, bz = 0.f, bw = 0.f;
    if (bias) {
        bx = bias[n0 + tx * 4 + 0]; by = bias[n0 + tx * 4 + 1];
        bz = bias[n0 + tx * 4 + 2]; bw = bias[n0 + tx * 4 + 3];
    }
#pragma unroll
    for (int ii = 0; ii < 4; ii++) {
        float4 o;
        o.x = acc[ii][0] + bx; o.y = acc[ii][1] + by; o.z = acc[ii][2] + bz; o.w = acc[ii][3] + bw;
        *reinterpret_cast<float4*>(C + (size_t)(m0 + ty * 4 + ii) * N + n0 + tx * 4) = o;
    }
}

// ---------------- e_src / e_dst ----------------
__global__ void k_se(const float* __restrict__ h, const float* __restrict__ ga,
                     float* __restrict__ esrc, float* __restrict__ edst, int total) {
    int idx = blockIdx.x * blockDim.x + threadIdx.x;
    if (idx >= total) return;
    int n = idx & (NT - 1);
    int hh = (idx >> 10) & 7;
    int b = idx >> 13;
    const float4* hr = reinterpret_cast<const float4*>(h + ((size_t)(b * NT + n)) * HID + hh * HD);
    const float4* as = reinterpret_cast<const float4*>(ga + hh * 2 * HD);
    const float4* ad = reinterpret_cast<const float4*>(ga + hh * 2 * HD + HD);
    float s = 0.f, d = 0.f;
#pragma unroll
    for (int i = 0; i < 16; i++) {
        float4 hv = hr[i], a1 = as[i], a2 = ad[i];
        s += hv.x * a1.x + hv.y * a1.y + hv.z * a1.z + hv.w * a1.w;
        d += hv.x * a2.x + hv.y * a2.y + hv.z * a2.z + hv.w * a2.w;
    }
    esrc[idx] = s;
    edst[idx] = d;
}

// ---------------- fused GAT attention (flash-style online softmax + P@H) ----------------
// grid = 1024 CTAs: blockIdx.x = h + 8*(b + 8*iblk); 256 threads
#define ATTN_SMEM_FLOATS (3 * 64 * 68 + 1024 + 4 * 64)
__global__ void __launch_bounds__(256) k_attn(
    const float* __restrict__ gh, const float* __restrict__ esrc,
    const float* __restrict__ edst, const float* __restrict__ twm,
    float* __restrict__ nodeout, int nb) {
    extern __shared__ float sm[];
    float* h_s = sm;                    // [64][68]
    float* tw_s = h_s + 64 * 68;        // [64][68]
    float* p_s = tw_s + 64 * 68;        // [64][68], layout [j][i]
    float* edst_s = p_s + 64 * 68;      // [1024]
    float* esrc_s = edst_s + 1024;      // [64]
    float* m_s = esrc_s + 64;           // [64]
    float* l_s = m_s + 64;              // [64]
    float* al_s = l_s + 64;             // [64]

    int t = threadIdx.x;
    int hh = blockIdx.x & 7;
    int rem = blockIdx.x >> 3;
    int b = rem & 7;
    int iblk = rem >> 3;
    int i0 = iblk * 64;
    int bh = (nb == 1) ? 0 : b;

    const float* ed = edst + (size_t)(bh * NH + hh) * NT;
    for (int u = t; u < NT; u += 256) edst_s[u] = ed[u];
    if (t < 64) {
        esrc_s[t] = esrc[(size_t)(bh * NH + hh) * NT + i0 + t];
        m_s[t] = -1e30f;
        l_s[t] = 0.f;
    }

    int ty = t >> 4, tx = t & 15;
    float acc[4][4] = {};

    int pi = t >> 2;   // phase-1 row
    int q = t & 3;

    const float* hbase = gh + (size_t)bh * NT * HID + hh * HD;
    const float* twbase = twm + ((size_t)b * NT + i0) * NT;

    int lr = t >> 2;               // tile-load row (0..63)
    int lc = (t & 3) * 16;         // tile-load col start

    __syncthreads();

    for (int j0 = 0; j0 < NT; j0 += 64) {
        // cooperative loads: h tile [64j][64d], twm tile [64i][64j]
        {
            const float4* src = reinterpret_cast<const float4*>(hbase + (size_t)(j0 + lr) * HID + lc);
            float4* dst = reinterpret_cast<float4*>(h_s + lr * 68 + lc);
            dst[0] = src[0]; dst[1] = src[1]; dst[2] = src[2]; dst[3] = src[3];
            const float4* ts = reinterpret_cast<const float4*>(twbase + (size_t)lr * NT + j0 + lc);
            float4* td = reinterpret_cast<float4*>(tw_s + lr * 68 + lc);
            td[0] = ts[0]; td[1] = ts[1]; td[2] = ts[2]; td[3] = ts[3];
        }
        __syncthreads();

        // phase 1: e + online softmax for row pi (4 threads/row, 16 j each)
        float es = esrc_s[pi];
        float e_reg[16];
        float lmax = -1e30f;
#pragma unroll
        for (int jj = 0; jj < 16; jj++) {
            int j = q + 4 * jj;
            float tw = tw_s[pi * 68 + j];
            float raw = es + edst_s[j0 + j];
            float leak = raw > 0.f ? raw : 0.2f * raw;
            float e = (tw < 0.f) ? -1e30f : leak * tw;
            e_reg[jj] = e;
            lmax = fmaxf(lmax, e);
        }
        lmax = fmaxf(lmax, __shfl_xor_sync(0xffffffffu, lmax, 1));
        lmax = fmaxf(lmax, __shfl_xor_sync(0xffffffffu, lmax, 2));
        float mold = m_s[pi];
        float mnew = fmaxf(mold, lmax);
        float lsum = 0.f;
#pragma unroll
        for (int jj = 0; jj < 16; jj++) {
            int j = q + 4 * jj;
            float p = expf(e_reg[jj] - mnew);
            p_s[j * 68 + pi] = p;
            lsum += p;
        }
        lsum += __shfl_xor_sync(0xffffffffu, lsum, 1);
        lsum += __shfl_xor_sync(0xffffffffu, lsum, 2);
        if (q == 0) {
            float alpha = expf(mold - mnew);
            al_s[pi] = alpha;
            m_s[pi] = mnew;
            l_s[pi] = l_s[pi] * alpha + lsum;
        }
        __syncthreads();

        // phase 2: acc = acc*alpha + P^T tile GEMM (4x4 per thread)
        float a0 = al_s[ty * 4 + 0], a1 = al_s[ty * 4 + 1];
        float a2 = al_s[ty * 4 + 2], a3 = al_s[ty * 4 + 3];
#pragma unroll
        for (int c = 0; c < 4; c++) {
            acc[0][c] *= a0; acc[1][c] *= a1; acc[2][c] *= a2; acc[3][c] *= a3;
        }
#pragma unroll 4
        for (int j = 0; j < 64; j++) {
            float4 pv = *reinterpret_cast<const float4*>(p_s + j * 68 + ty * 4);
            float4 hv = *reinterpret_cast<const float4*>(h_s + j * 68 + tx * 4);
            acc[0][0] += pv.x * hv.x; acc[0][1] += pv.x * hv.y; acc[0][2] += pv.x * hv.z; acc[0][3] += pv.x * hv.w;
            acc[1][0] += pv.y * hv.x; acc[1][1] += pv.y * hv.y; acc[1][2] += pv.y * hv.z; acc[1][3] += pv.y * hv.w;
            acc[2][0] += pv.z * hv.x; acc[2][1] += pv.z * hv.y; acc[2][2] += pv.z * hv.z; acc[2][3] += pv.z * hv.w;
            acc[3][0] += pv.w * hv.x; acc[3][1] += pv.w * hv.y; acc[3][2] += pv.w * hv.z; acc[3][3] += pv.w * hv.w;
        }
        __syncthreads();
    }

    // finalize: out = elu(acc / l)
#pragma unroll
    for (int ii = 0; ii < 4; ii++) {
        int i = ty * 4 + ii;
        float inv = 1.f / l_s[i];
        float v0 = acc[ii][0] * inv, v1 = acc[ii][1] * inv;
        float v2 = acc[ii][2] * inv, v3 = acc[ii][3] * inv;
        float4 o;
        o.x = v0 > 0.f ? v0 : (expf(v0) - 1.f);
        o.y = v1 > 0.f ? v1 : (expf(v1) - 1.f);
        o.z = v2 > 0.f ? v2 : (expf(v2) - 1.f);
        o.w = v3 > 0.f ? v3 : (expf(v3) - 1.f);
        *reinterpret_cast<float4*>(nodeout + ((size_t)b * NT + i0 + i) * HID + hh * HD + tx * 4) = o;
    }
}

// ---------------- final MLP ----------------
__global__ void k_final(const float* __restrict__ node, const int* __restrict__ topic_ids,
                        const float* __restrict__ attractiveness,
                        const float* __restrict__ aW, const float* __restrict__ ab,
                        const float* __restrict__ f1W, const float* __restrict__ f1b,
                        const float* __restrict__ f2W, const float* __restrict__ f2b,
                        float* __restrict__ out) {
    int b = blockIdx.x;
    int t = threadIdx.x;  // 512
    __shared__ float comb[HID];
    __shared__ float red[16];
    int tid = topic_ids[b];
    float av = attractiveness[b];
    comb[t] = node[((size_t)b * NT + tid) * HID + t] + av * aW[t] + ab[t];
    __syncthreads();
    float acc = f1b[t];
    const float4* w = reinterpret_cast<const float4*>(f1W + (size_t)t * HID);
    const float4* c4 = reinterpret_cast<const float4*>(comb);
#pragma unroll 8
    for (int o = 0; o < HID / 4; o++) {
        float4 wv = w[o], cv = c4[o];
        acc += wv.x * cv.x + wv.y * cv.y + wv.z * cv.z + wv.w * cv.w;
    }
    acc = fmaxf(acc, 0.f);
    float p = acc * f2W[t];
#pragma unroll
    for (int s = 16; s; s >>= 1) p += __shfl_xor_sync(0xffffffffu, p, s);
    if ((t & 31) == 0) red[t >> 5] = p;
    __syncthreads();
    if (t < 16) {
        float v = red[t];
#pragma unroll
        for (int s = 8; s; s >>= 1) v += __shfl_xor_sync(0xffffu, v, s);
        if (t == 0) out[b] = v + f2b[0];
    }
}

// ---------------- launch ----------------
extern "C" void kernel_launch(void* const* d_in, const int* in_sizes, int n_in,
                              void* d_out, int out_size) {
    const int*   topic_ids = (const int*)d_in[0];
    const int*   adj       = (const int*)d_in[1];
    const float* timem     = (const float*)d_in[2];
    const float* attract   = (const float*)d_in[3];
    const float* emb       = (const float*)d_in[4];
    const float* sW        = (const float*)d_in[5];
    const float* sb        = (const float*)d_in[6];
    const float* aW        = (const float*)d_in[7];
    const float* ab        = (const float*)d_in[8];
    const float* gW        = (const float*)d_in[9];
    const float* ga        = (const float*)d_in[10];
    const float* f1W       = (const float*)d_in[11];
    const float* f1b       = (const float*)d_in[12];
    const float* f2W       = (const float*)d_in[13];
    const float* f2b       = (const float*)d_in[14];
    float* out = (float*)d_out;

    void *pv;
    cudaGetSymbolAddress(&pv, g_twm);    float* twm  = (float*)pv;
    cudaGetSymbolAddress(&pv, g_struct); float* gstr = (float*)pv;
    cudaGetSymbolAddress(&pv, g_bt);     float* bt   = (float*)pv;
    cudaGetSymbolAddress(&pv, g_h);      float* h    = (float*)pv;
    cudaGetSymbolAddress(&pv, g_node);   float* node = (float*)pv;
    cudaGetSymbolAddress(&pv, g_esrc);   float* esrc = (float*)pv;
    cudaGetSymbolAddress(&pv, g_edst);   float* edst = (float*)pv;

    const int attn_smem = ATTN_SMEM_FLOATS * (int)sizeof(float);  // 57344 B
    cudaFuncSetAttribute(k_attn, cudaFuncAttributeMaxDynamicSharedMemorySize, attn_smem);

    int n4 = (BATCH * NT * NT) / 4;
    k_init<<<1, 1>>>();
    k_tmax<<<2048, 256>>>(reinterpret_cast<const float4*>(timem), n4);
    k_twm<<<4096, 256>>>(reinterpret_cast<const float4*>(timem),
                         reinterpret_cast<const int4*>(adj), n4);

    // struct = emb @ struct_W^T + b
    k_transB<<<(TD * HID) / 256, 256>>>(sW, bt);
    k_gemm<<<dim3(NT / 64, HID / 64), 256>>>(emb, bt, gstr, sb, TD, HID);

    for (int l = 0; l < 2; l++) {
        int nb = (l == 0) ? 1 : BATCH;
        k_transW<<<(HID * HID) / 256, 256>>>(gW + (size_t)l * NH * HID * HD, bt);
        const float* node_in = (l == 0) ? gstr : node;
        k_gemm<<<dim3(nb * NT / 64, HID / 64), 256>>>(node_in, bt, h, nullptr, HID, HID);
        k_se<<<(nb * NH * NT) / 256, 256>>>(h, ga + (size_t)l * NH * 2 * HD, esrc, edst, nb * NH * NT);
        k_attn<<<BATCH * NH * (NT / 64), 256, attn_smem>>>(h, esrc, edst, twm, node, nb);
    }

    k_final<<<BATCH, 512>>>(node, topic_ids, attract, aW, ab, f1W, f1b, f2W, f2b, out);
}